// round 13
// baseline (speedup 1.0000x reference)
#include <cuda_runtime.h>
#include <stdint.h>

// Problem shape (fixed by the dataset)
#define BATCH   8192
#define IN_DIM  4096
#define N_RULES 2048
#define KWORDS  128              // u32 bit-words along k
#define NBG     8                // big rule-groups (256 rules each)
#define NPACK   1024             // pack tiles: 8 bg x 128 w-layers (group-major)
#define NOUT    1024             // out tiles:  64 rg32 x 16 row-slices
#define GRID    444              // 148 SMs x 3 CTAs -> all resident in wave 1

// Scratch (device globals — no allocation allowed)
__device__ uint32_t g_wbitsT[KWORDS * N_RULES];   // TRANSPOSED: [w][r]
__device__ unsigned g_done [NBG];   // pack tiles completed per big group
__device__ unsigned g_odone[NBG];   // out tiles completed per big group
// Both counters are SELF-RESETTING: the CTA finishing the last out tile of a
// group zeroes them, so every graph replay starts from the all-zero state.

// Rare path: recompute out[b,r] DIRECTLY from x and wbitsT. res > 0 iff some
// k has W-bit set AND x[b,k] != 1.0f. Exits on the first such k.
__device__ __noinline__ float conj_direct(const float* __restrict__ x,
                                          int b, int r) {
    const float* xb = x + (size_t)b * IN_DIM;
    for (int i = 0; i < KWORDS; i++) {
        uint32_t wd = __ldcg(&g_wbitsT[(size_t)i * N_RULES + r]);
        while (wd) {
            int j = __ffs(wd) - 1;
            if (xb[i * 32 + j] != 1.0f) return 0.0f;
            wd &= wd - 1;
        }
    }
    return 1.0f;
}

// ---------------------------------------------------------------------------
// Fused persistent kernel, TWO item classes over a grid-stride loop:
//   ids [0, 1024):    pack tile (bg = id>>7, w-layer = id&127)  — never waits
//   ids [1024, 2048): out tile — waits only on g_done[bg] == 128 (all pack
//                     ids of bg are strictly smaller ids -> no deadlock).
// Overlaps the 32MB DRAM read stream (pack) with the 64MB write stream (out).
// ---------------------------------------------------------------------------
__global__ void __launch_bounds__(256, 3)
fused_kernel(const float* __restrict__ W, const float* __restrict__ x,
             float* __restrict__ out) {
    __shared__ uint32_t sm[32 * 64];           // pack: bool-byte tile (8KB)
    uint32_t* sm_red = sm;                     // out: [8][32] partial folds
    uint32_t* s_w    = sm + 256;               // out: folded wany per rule
    float*    s_val  = (float*)(sm + 288);     // out: empty-rule answer
    uint32_t* s_flag = sm + 320;
    int tid = threadIdx.x;

    for (int p = blockIdx.x; p < NPACK + NOUT; p += GRID) {
        __syncthreads();                       // smem reuse guard between items
        if (p < NPACK) {
            // ---------------- pack tile: 32 k-rows x 256 rules ----------------
            int bg = p >> 7;                   // big group (256 rules)
            int w  = p & 127;                  // w-layer
            const float4* W4 = reinterpret_cast<const float4*>(W);
            size_t base = (size_t)(w * 32) * (N_RULES / 4) + bg * 64;
#pragma unroll
            for (int u = 0; u < 8; u++) {      // 8 independent coalesced loads
                int fi  = u * 256 + tid;
                int row = fi >> 6;
                int c4  = fi & 63;
                float4 v = W4[base + (size_t)row * (N_RULES / 4) + c4];
                uint32_t bb = (v.x > 0.5f ? 0x01u : 0u) |
                              (v.y > 0.5f ? 0x0100u : 0u) |
                              (v.z > 0.5f ? 0x010000u : 0u) |
                              (v.w > 0.5f ? 0x01000000u : 0u);
                sm[row * 64 + c4] = bb;
            }
            __syncthreads();
            const uint8_t* sm8 = reinterpret_cast<const uint8_t*>(sm);
            uint32_t word = 0;
#pragma unroll
            for (int j = 0; j < 32; j++)
                word |= (uint32_t)(sm8[j * 256 + tid] & 1u) << j;
            g_wbitsT[(size_t)w * N_RULES + bg * 256 + tid] = word;
            __threadfence();                   // release stores
            __syncthreads();
            if (tid == 0) atomicAdd(&g_done[bg], 1u);
        } else {
            // ---------------- out tile: 32 rules x 512 rows -------------------
            int q     = p - NPACK;
            int bg    = q >> 7;
            int rg    = bg * 8 + (q & 7);      // 32-rule group [0, 64)
            int slice = (q >> 3) & 15;
            int b0    = slice * 512;

            if (tid == 0) {                    // acquire group's pack tiles
                while (((volatile unsigned*)g_done)[bg] < 128u) __nanosleep(32);
                __threadfence();
            }
            __syncthreads();

            {   // fold wany for 32 rules over 128 w-layers (L2-resident 16KB)
                int r  = rg * 32 + (tid & 31);
                int wc = tid >> 5;             // 0..7
                uint32_t o = 0;
#pragma unroll
                for (int i = 0; i < 16; i++)
                    o |= __ldcg(&g_wbitsT[(size_t)(wc * 16 + i) * N_RULES + r]);
                sm_red[wc * 32 + (tid & 31)] = o;
            }
            __syncthreads();
            if (tid < 32) {
                uint32_t o = sm_red[tid] | sm_red[32 + tid] | sm_red[64 + tid] |
                             sm_red[96 + tid] | sm_red[128 + tid] |
                             sm_red[160 + tid] | sm_red[192 + tid] |
                             sm_red[224 + tid];
                s_w[tid]   = o;
                s_val[tid] = (o == 0u) ? 1.0f : 0.0f;
                uint32_t any = __reduce_or_sync(0xFFFFFFFFu, o);
                if (tid == 0) *s_flag = (any == 0u) ? 1u : 0u;
            }
            __syncthreads();

            bool empty  = (*s_flag != 0u);
            int  chunk  = tid & 7;             // float4 chunk within 32 rules
            int  rowoff = tid >> 3;            // 0..31
            float4 v0 = *reinterpret_cast<const float4*>(s_val + chunk * 4);
            float4* o4 = reinterpret_cast<float4*>(out);
#pragma unroll
            for (int it = 0; it < 16; it++) {
                int b = b0 + it * 32 + rowoff;
                float4 o;
                if (empty) {
                    o = v0;                    // dominant path: all rules empty
                } else {
                    int r0 = rg * 32 + chunk * 4;
                    o.x = (s_w[chunk*4+0] == 0u) ? 1.0f : conj_direct(x, b, r0+0);
                    o.y = (s_w[chunk*4+1] == 0u) ? 1.0f : conj_direct(x, b, r0+1);
                    o.z = (s_w[chunk*4+2] == 0u) ? 1.0f : conj_direct(x, b, r0+2);
                    o.w = (s_w[chunk*4+3] == 0u) ? 1.0f : conj_direct(x, b, r0+3);
                }
                o4[(size_t)b * 512 + rg * 8 + chunk] = o;
            }

            // Self-reset: the CTA completing this group's LAST out tile zeroes
            // both counters. Every wait on g_done[bg] happened strictly before
            // its g_odone increment, so no reader can observe the reset early.
            __syncthreads();
            if (tid == 0) {
                unsigned old = atomicAdd(&g_odone[bg], 1u);
                if (old == 127u) {
                    ((volatile unsigned*)g_done)[bg]  = 0u;
                    ((volatile unsigned*)g_odone)[bg] = 0u;
                    __threadfence();
                }
            }
        }
    }
}

// ---------------------------------------------------------------------------
extern "C" void kernel_launch(void* const* d_in, const int* in_sizes, int n_in,
                              void* d_out, int out_size) {
    const float* x = (const float*)d_in[0];   // [BATCH, IN_DIM]
    const float* W = (const float*)d_in[1];   // [IN_DIM, N_RULES]
    float* out = (float*)d_out;               // [BATCH, N_RULES]

    (void)in_sizes; (void)n_in; (void)out_size;

    fused_kernel<<<GRID, 256>>>(W, x, out);   // single launch, self-resetting
}

// round 14
// speedup vs baseline: 1.2076x; 1.2076x over previous
#include <cuda_runtime.h>
#include <stdint.h>

// Problem shape (fixed by the dataset)
#define BATCH   8192
#define IN_DIM  4096
#define N_RULES 2048
#define SPLITS  256              // k-splits of 16 rows each (256*16 = 4096)
#define ROWS_PS 16

// Scratch (device globals — no allocation allowed).
// g_part[s][r] = 1 iff any W[k,r] > 0.5 for k in split s. Fully overwritten
// every call -> replay-deterministic, no init, no atomics.
__device__ uint8_t g_part[SPLITS * N_RULES];     // 512 KB

// Cold path: recompute out[b,r] directly from W and x. res > 0 iff some k has
// W[k,r] > 0.5 AND x[b,k] != 1.0f. Early-exits; never runs for typical data.
__device__ __noinline__ float conj_direct(const float* __restrict__ W,
                                          const float* __restrict__ x,
                                          int b, int r) {
    const float* xb = x + (size_t)b * IN_DIM;
    for (int k = 0; k < IN_DIM; k++) {
        if (W[(size_t)k * N_RULES + r] > 0.5f && xb[k] != 1.0f) return 0.0f;
    }
    return 1.0f;
}

// ---------------------------------------------------------------------------
// Kernel A: pure read-reduce. Block = (split s, rule-half h): 16 rows x 1024
// rules. Thread owns 4 consecutive rules (one float4 column): 16 INDEPENDENT
// coalesced float4 loads -> register OR -> one uchar4 store. No smem, no
// transpose, no dependency chains: the load stream is unconstrained.
// ---------------------------------------------------------------------------
__global__ __launch_bounds__(256) void wpart_kernel(const float* __restrict__ W) {
    int t  = threadIdx.x;
    int s  = blockIdx.x >> 1;            // split [0, 256)
    int h  = blockIdx.x & 1;             // rule half
    int c4 = h * 256 + t;                // float4 column [0, 512)

    const float4* W4 = reinterpret_cast<const float4*>(W);
    size_t base = (size_t)s * ROWS_PS * (N_RULES / 4) + c4;
    bool a0 = false, a1 = false, a2 = false, a3 = false;
#pragma unroll
    for (int j = 0; j < ROWS_PS; j++) {
        float4 v = W4[base + (size_t)j * (N_RULES / 4)];
        a0 |= (v.x > 0.5f);
        a1 |= (v.y > 0.5f);
        a2 |= (v.z > 0.5f);
        a3 |= (v.w > 0.5f);
    }
    uchar4 rbyte;
    rbyte.x = a0; rbyte.y = a1; rbyte.z = a2; rbyte.w = a3;
    reinterpret_cast<uchar4*>(g_part)[(size_t)s * (N_RULES / 4) + c4] = rbyte;
}

// ---------------------------------------------------------------------------
// Kernel B: output [BATCH, N_RULES]. Block owns 32 rules x 512 rows.
// Fold the 256 per-split empty-bytes for its 32 rules (8KB, L2-resident),
// then stream coalesced float4 writes. Grid 64 x 16 = 1024 blocks.
// x and W are touched ONLY on the cold path (non-empty rule).
// ---------------------------------------------------------------------------
__global__ __launch_bounds__(256) void out_kernel(const float* __restrict__ W,
                                                  const float* __restrict__ x,
                                                  float* __restrict__ out) {
    __shared__ uint32_t sm_red[8][32];
    __shared__ __align__(16) float s_val[32];   // empty-rule answer per rule
    __shared__ uint32_t s_w[32];                // nonzero <=> rule non-empty
    __shared__ uint32_t s_flag;
    int tid = threadIdx.x;
    int rg  = blockIdx.x & 63;                  // rule-group: 32 rules
    int b0  = (blockIdx.x >> 6) * 512;          // row-slice base

    {   // fold empties: warp wi covers splits [wi*32, +32), lane = rule
        int lane = tid & 31, wi = tid >> 5;
        uint32_t acc = 0;
#pragma unroll
        for (int i = 0; i < 32; i++) {
            acc |= g_part[(size_t)(wi * 32 + i) * N_RULES + rg * 32 + lane];
        }
        sm_red[wi][lane] = acc;
    }
    __syncthreads();
    if (tid < 32) {
        uint32_t o = sm_red[0][tid] | sm_red[1][tid] | sm_red[2][tid] |
                     sm_red[3][tid] | sm_red[4][tid] | sm_red[5][tid] |
                     sm_red[6][tid] | sm_red[7][tid];
        s_w[tid]   = o;
        s_val[tid] = (o == 0u) ? 1.0f : 0.0f;
        uint32_t any = __reduce_or_sync(0xFFFFFFFFu, o);
        if (tid == 0) s_flag = (any == 0u) ? 1u : 0u;
    }
    __syncthreads();

    bool empty  = (s_flag != 0u);
    int  chunk  = tid & 7;                      // float4 chunk within 32 rules
    int  rowoff = tid >> 3;                     // 0..31
    float4 v0 = *reinterpret_cast<const float4*>(s_val + chunk * 4);
    float4* o4 = reinterpret_cast<float4*>(out);

#pragma unroll
    for (int it = 0; it < 16; it++) {
        int b = b0 + it * 32 + rowoff;
        float4 o;
        if (empty) {
            o = v0;                             // dominant path
        } else {
            int r0 = rg * 32 + chunk * 4;
            o.x = (s_w[chunk*4+0] == 0u) ? 1.0f : conj_direct(W, x, b, r0 + 0);
            o.y = (s_w[chunk*4+1] == 0u) ? 1.0f : conj_direct(W, x, b, r0 + 1);
            o.z = (s_w[chunk*4+2] == 0u) ? 1.0f : conj_direct(W, x, b, r0 + 2);
            o.w = (s_w[chunk*4+3] == 0u) ? 1.0f : conj_direct(W, x, b, r0 + 3);
        }
        o4[(size_t)b * 512 + rg * 8 + chunk] = o;
    }
}

// ---------------------------------------------------------------------------
extern "C" void kernel_launch(void* const* d_in, const int* in_sizes, int n_in,
                              void* d_out, int out_size) {
    const float* x = (const float*)d_in[0];   // [BATCH, IN_DIM]
    const float* W = (const float*)d_in[1];   // [IN_DIM, N_RULES]
    float* out = (float*)d_out;               // [BATCH, N_RULES]

    (void)in_sizes; (void)n_in; (void)out_size;

    wpart_kernel<<<SPLITS * 2, 256>>>(W);     // 512 blocks, pure read-reduce
    out_kernel<<<64 * 16, 256>>>(W, x, out);  // 1024 blocks
}